// round 1
// baseline (speedup 1.0000x reference)
#include <cuda_runtime.h>
#include <cstdint>

// Problem constants
#define B_TOT 12288   // features(4096) + queue(8192)
#define N_OUT 4096
#define KCLS  1000
#define DDIM  256
#define INV_EPS 20.0f // 1/0.05

// Scratch (static device globals; allocation-free at runtime)
__device__ float  g_E[B_TOT * KCLS];     // exp(logits/eps), row-major [b, k]  (~49 MB)
__device__ float  g_Hs[DDIM * KCLS];     // row-normalized head
__device__ float  g_invFn[B_TOT];        // 1/||feat_row||
__device__ float  g_u[KCLS];
__device__ float  g_r[KCLS];
__device__ float  g_c[B_TOT];
__device__ double g_S;

__device__ __forceinline__ float warp_sum(float v) {
    #pragma unroll
    for (int o = 16; o > 0; o >>= 1) v += __shfl_down_sync(0xFFFFFFFFu, v, o);
    return v;
}

// ---------------------------------------------------------------------------
// 1. Normalize head rows: Hs[d,k] = head[d,k] / max(||head[d,:]||, 1e-12)
// ---------------------------------------------------------------------------
__global__ void k_head_norm(const float* __restrict__ head) {
    int d = blockIdx.x;
    const float* row = head + (size_t)d * KCLS;
    float ss = 0.f;
    for (int k = threadIdx.x; k < KCLS; k += blockDim.x) {
        float v = row[k];
        ss += v * v;
    }
    __shared__ float sred[256];
    ss = warp_sum(ss);
    if ((threadIdx.x & 31) == 0) sred[threadIdx.x >> 5] = ss;
    __syncthreads();
    if (threadIdx.x < 8) {
        float s = sred[threadIdx.x];
        #pragma unroll
        for (int o = 4; o > 0; o >>= 1) s += __shfl_down_sync(0xFFu, s, o);
        if (threadIdx.x == 0) sred[0] = 1.0f / fmaxf(sqrtf(s), 1e-12f);
    }
    __syncthreads();
    float inv = sred[0];
    for (int k = threadIdx.x; k < KCLS; k += blockDim.x)
        g_Hs[(size_t)d * KCLS + k] = row[k] * inv;
}

// ---------------------------------------------------------------------------
// 2. Per-row inverse norms of combined feature matrix (one warp per row)
// ---------------------------------------------------------------------------
__global__ void k_feat_norm(const float* __restrict__ features,
                            const float* __restrict__ queue) {
    int gwarp = (blockIdx.x * blockDim.x + threadIdx.x) >> 5;
    int lane  = threadIdx.x & 31;
    if (gwarp >= B_TOT) return;
    const float* row = (gwarp < N_OUT) ? (features + (size_t)gwarp * DDIM)
                                       : (queue + (size_t)(gwarp - N_OUT) * DDIM);
    const float4* r4 = reinterpret_cast<const float4*>(row);
    float ss = 0.f;
    #pragma unroll
    for (int i = 0; i < 2; i++) {
        float4 v = r4[lane + i * 32];
        ss += v.x * v.x + v.y * v.y + v.z * v.z + v.w * v.w;
    }
    ss = warp_sum(ss);
    if (lane == 0) g_invFn[gwarp] = 1.0f / fmaxf(sqrtf(ss), 1e-12f);
}

// ---------------------------------------------------------------------------
// 3. Zero accumulators (must run every launch: graph is replayed)
// ---------------------------------------------------------------------------
__global__ void k_zero() {
    int t = blockIdx.x * blockDim.x + threadIdx.x;
    if (t < KCLS) g_u[t] = 0.f;
    if (t == 0)  g_S = 0.0;
}

// ---------------------------------------------------------------------------
// 4. GEMM + exp: E[b,k] = exp(20 * invFn[b] * sum_d F[b,d]*Hs[d,k])
//    Also accumulates u_k = sum_b E[b,k]  (c=1 initial) and S = sum E.
//    BM=128, BN=64, BK=16, 256 threads, TM=8 x TN=4 per thread.
// ---------------------------------------------------------------------------
#define BM 128
#define BN 64
#define BK 16
__global__ __launch_bounds__(256) void k_gemm_exp(const float* __restrict__ features,
                                                  const float* __restrict__ queue) {
    __shared__ float As[BK][BM];
    __shared__ float Bs[BK][BN];
    __shared__ float scol[BN];

    int b0 = blockIdx.y * BM;
    int n0 = blockIdx.x * BN;
    int tid = threadIdx.x;
    int tx = tid & 15;   // n-direction (16 threads * TN=4 = 64)
    int ty = tid >> 4;   // m-direction (16 threads * TM=8 = 128)

    const float* Asrc = (b0 < N_OUT) ? (features + (size_t)b0 * DDIM)
                                     : (queue + (size_t)(b0 - N_OUT) * DDIM);

    float acc[8][4];
    #pragma unroll
    for (int i = 0; i < 8; i++)
        #pragma unroll
        for (int j = 0; j < 4; j++) acc[i][j] = 0.f;

    for (int k0 = 0; k0 < DDIM; k0 += BK) {
        // Load A tile 128x16 (512 float4, 2 per thread), store transposed
        #pragma unroll
        for (int i = 0; i < 2; i++) {
            int idx  = tid + i * 256;      // float4 index
            int row  = idx >> 2;           // 4 float4 per row
            int col4 = idx & 3;
            float4 v = *reinterpret_cast<const float4*>(Asrc + (size_t)row * DDIM + k0 + col4 * 4);
            As[col4 * 4 + 0][row] = v.x;
            As[col4 * 4 + 1][row] = v.y;
            As[col4 * 4 + 2][row] = v.z;
            As[col4 * 4 + 3][row] = v.w;
        }
        // Load B tile 16x64 (1024 floats, 4 per thread)
        #pragma unroll
        for (int i = 0; i < 4; i++) {
            int idx = tid + i * 256;
            int kk  = idx >> 6;
            int n   = idx & 63;
            Bs[kk][n] = (n0 + n < KCLS) ? g_Hs[(size_t)(k0 + kk) * KCLS + n0 + n] : 0.f;
        }
        __syncthreads();
        #pragma unroll
        for (int kk = 0; kk < BK; kk++) {
            float a[8], bv[4];
            #pragma unroll
            for (int i = 0; i < 8; i++) a[i] = As[kk][ty * 8 + i];
            #pragma unroll
            for (int j = 0; j < 4; j++) bv[j] = Bs[kk][tx * 4 + j];
            #pragma unroll
            for (int i = 0; i < 8; i++)
                #pragma unroll
                for (int j = 0; j < 4; j++) acc[i][j] += a[i] * bv[j];
        }
        __syncthreads();
    }

    if (tid < BN) scol[tid] = 0.f;
    __syncthreads();

    int n = n0 + tx * 4;
    bool nvalid = (n < KCLS);   // KCLS % 4 == 0, so whole float4 is in or out
    if (nvalid) {
        float inv[8];
        #pragma unroll
        for (int i = 0; i < 8; i++) inv[i] = g_invFn[b0 + ty * 8 + i] * INV_EPS;
        float cp0 = 0.f, cp1 = 0.f, cp2 = 0.f, cp3 = 0.f;
        #pragma unroll
        for (int i = 0; i < 8; i++) {
            int b = b0 + ty * 8 + i;
            float4 e;
            e.x = __expf(acc[i][0] * inv[i]);
            e.y = __expf(acc[i][1] * inv[i]);
            e.z = __expf(acc[i][2] * inv[i]);
            e.w = __expf(acc[i][3] * inv[i]);
            *reinterpret_cast<float4*>(g_E + (size_t)b * KCLS + n) = e;
            cp0 += e.x; cp1 += e.y; cp2 += e.z; cp3 += e.w;
        }
        atomicAdd(&scol[tx * 4 + 0], cp0);
        atomicAdd(&scol[tx * 4 + 1], cp1);
        atomicAdd(&scol[tx * 4 + 2], cp2);
        atomicAdd(&scol[tx * 4 + 3], cp3);
    }
    __syncthreads();
    if (tid < BN && (n0 + tid) < KCLS) atomicAdd(&g_u[n0 + tid], scol[tid]);
    if (tid < 32) {
        float s = scol[tid] + scol[tid + 32];
        s = warp_sum(s);
        if (tid == 0) atomicAdd(&g_S, (double)s);
    }
}

// ---------------------------------------------------------------------------
// 5. r_k = S / (K * u_k); also re-zero u for the next accumulation
// ---------------------------------------------------------------------------
__global__ void k_fin_r() {
    int k = blockIdx.x * blockDim.x + threadIdx.x;
    if (k < KCLS) {
        double u = (double)g_u[k];
        g_r[k] = (float)(g_S / ((double)KCLS * u));
        g_u[k] = 0.f;
    }
}

// ---------------------------------------------------------------------------
// 6. Row reduce: v_b = sum_k E[b,k]*r_k ; c_b = S/(B*v_b).  One warp per row.
// ---------------------------------------------------------------------------
__global__ __launch_bounds__(256) void k_v_c() {
    __shared__ __align__(16) float rsh[KCLS];
    for (int k = threadIdx.x; k < KCLS; k += blockDim.x) rsh[k] = g_r[k];
    __syncthreads();
    int warp = threadIdx.x >> 5;
    int lane = threadIdx.x & 31;
    int b = blockIdx.x * 8 + warp;
    const float4* E4 = reinterpret_cast<const float4*>(g_E + (size_t)b * KCLS);
    const float4* r4 = reinterpret_cast<const float4*>(rsh);
    float v = 0.f;
    #pragma unroll
    for (int i = 0; i < 8; i++) {
        int idx = lane + i * 32;           // 0..255, 250 valid
        if (idx < KCLS / 4) {
            float4 e = E4[idx];
            float4 r = r4[idx];
            v += e.x * r.x + e.y * r.y + e.z * r.z + e.w * r.w;
        }
    }
    v = warp_sum(v);
    if (lane == 0) g_c[b] = (float)(g_S / ((double)B_TOT * (double)v));
}

// ---------------------------------------------------------------------------
// 7. Column reduce: u_k += sum_{b in chunk} E[b,k]*c_b  (atomics into g_u)
// ---------------------------------------------------------------------------
#define UCHUNK 128
__global__ __launch_bounds__(256) void k_u_pass() {
    __shared__ float csh[UCHUNK];
    int k  = blockIdx.x * 256 + threadIdx.x;
    int b0 = blockIdx.y * UCHUNK;
    if (threadIdx.x < UCHUNK) csh[threadIdx.x] = g_c[b0 + threadIdx.x];
    __syncthreads();
    if (k >= KCLS) return;
    const float* p = g_E + (size_t)b0 * KCLS + k;
    float acc = 0.f;
    #pragma unroll 8
    for (int i = 0; i < UCHUNK; i++) acc += p[(size_t)i * KCLS] * csh[i];
    atomicAdd(&g_u[k], acc);
}

// ---------------------------------------------------------------------------
// 8. Output: out[b,k] = (B/S) * r_k * c_b * E[b,k], b < 4096 (float32 out)
// ---------------------------------------------------------------------------
__global__ __launch_bounds__(256) void k_out(float* __restrict__ out) {
    int idx = blockIdx.x * 256 + threadIdx.x;           // float4 index
    const int TOT4 = N_OUT * KCLS / 4;
    if (idx >= TOT4) return;
    int b  = idx / (KCLS / 4);
    int k4 = idx - b * (KCLS / 4);
    float s = (float)((double)B_TOT / g_S) * g_c[b];
    float4 e = reinterpret_cast<const float4*>(g_E)[(size_t)b * (KCLS / 4) + k4];
    float4 r = reinterpret_cast<const float4*>(g_r)[k4];
    float4 o;
    o.x = s * r.x * e.x;
    o.y = s * r.y * e.y;
    o.z = s * r.z * e.z;
    o.w = s * r.w * e.w;
    reinterpret_cast<float4*>(out)[idx] = o;
}

// ---------------------------------------------------------------------------
extern "C" void kernel_launch(void* const* d_in, const int* in_sizes, int n_in,
                              void* d_out, int out_size) {
    const float* features = (const float*)d_in[0];
    const float* head     = (const float*)d_in[1];
    const float* queue    = (const float*)d_in[2];
    float* out = (float*)d_out;

    k_head_norm<<<256, 256>>>(head);
    k_feat_norm<<<(B_TOT * 32) / 256, 256>>>(features, queue);
    k_zero<<<4, 256>>>();
    k_gemm_exp<<<dim3((KCLS + BN - 1) / BN, B_TOT / BM), 256>>>(features, queue);
    // iter 1
    k_fin_r<<<4, 256>>>();
    k_v_c<<<B_TOT / 8, 256>>>();
    // iter 2
    k_u_pass<<<dim3(4, B_TOT / UCHUNK), 256>>>();
    k_fin_r<<<4, 256>>>();
    k_v_c<<<B_TOT / 8, 256>>>();
    // iter 3
    k_u_pass<<<dim3(4, B_TOT / UCHUNK), 256>>>();
    k_fin_r<<<4, 256>>>();
    k_v_c<<<B_TOT / 8, 256>>>();
    // output
    k_out<<<(N_OUT * KCLS / 4 + 255) / 256, 256>>>(out);
}

// round 3
// speedup vs baseline: 1.5270x; 1.5270x over previous
#include <cuda_runtime.h>
#include <cuda_bf16.h>
#include <cstdint>

// Problem constants
#define B_TOT 12288   // features(4096) + queue(8192)
#define N_OUT 4096
#define KCLS  1000
#define KPAD  1024
#define DDIM  256
#define INV_EPS 20.0f

// ---------------------------------------------------------------------------
// Device scratch (allocation-free)
// ---------------------------------------------------------------------------
__device__ float           g_E[B_TOT * KPAD];     // exp(logits/eps), [b, 1024] (50 MB)
__device__ __nv_bfloat16   g_Ahi[B_TOT * DDIM];   // normalized features, hi
__device__ __nv_bfloat16   g_Alo[B_TOT * DDIM];   // normalized features, lo
__device__ __nv_bfloat16   g_Bhi[KPAD * DDIM];    // normalized head^T, hi (pad rows stay 0)
__device__ __nv_bfloat16   g_Blo[KPAD * DDIM];    // normalized head^T, lo
__device__ float           g_u[KPAD];
__device__ float           g_r[KPAD];
__device__ float           g_c[B_TOT];
__device__ double          g_S;

__device__ __forceinline__ float warp_sum(float v) {
    #pragma unroll
    for (int o = 16; o > 0; o >>= 1) v += __shfl_down_sync(0xFFFFFFFFu, v, o);
    return v;
}

__device__ __forceinline__ uint32_t smem_u32(const void* p) {
    uint32_t a;
    asm("{ .reg .u64 t; cvta.to.shared.u64 t, %1; cvt.u32.u64 %0, t; }" : "=r"(a) : "l"(p));
    return a;
}

#define SW128(o) ((o) ^ (((o) >> 3) & 0x70))

__device__ __forceinline__ void ldsm_x4(uint32_t& r0, uint32_t& r1, uint32_t& r2, uint32_t& r3,
                                        uint32_t addr) {
    asm volatile("ldmatrix.sync.aligned.m8n8.x4.shared.b16 {%0,%1,%2,%3}, [%4];"
                 : "=r"(r0), "=r"(r1), "=r"(r2), "=r"(r3) : "r"(addr));
}

__device__ __forceinline__ void mma_bf16(float* d, const uint32_t* a, const uint32_t* b) {
    asm volatile(
        "mma.sync.aligned.m16n8k16.row.col.f32.bf16.bf16.f32 "
        "{%0,%1,%2,%3}, {%4,%5,%6,%7}, {%8,%9}, {%0,%1,%2,%3};"
        : "+f"(d[0]), "+f"(d[1]), "+f"(d[2]), "+f"(d[3])
        : "r"(a[0]), "r"(a[1]), "r"(a[2]), "r"(a[3]), "r"(b[0]), "r"(b[1]));
}

// ---------------------------------------------------------------------------
// 1. Normalize feature rows; split into bf16 hi/lo. One warp per row.
// ---------------------------------------------------------------------------
__global__ __launch_bounds__(256) void k_prep_feat(const float* __restrict__ features,
                                                   const float* __restrict__ queue) {
    int gwarp = (blockIdx.x * blockDim.x + threadIdx.x) >> 5;
    int lane  = threadIdx.x & 31;
    if (gwarp >= B_TOT) return;
    const float* row = (gwarp < N_OUT) ? (features + (size_t)gwarp * DDIM)
                                       : (queue + (size_t)(gwarp - N_OUT) * DDIM);
    float x[8];
    const float4* r4 = reinterpret_cast<const float4*>(row + lane * 8);
    float4 v0 = r4[0], v1 = r4[1];
    x[0]=v0.x; x[1]=v0.y; x[2]=v0.z; x[3]=v0.w;
    x[4]=v1.x; x[5]=v1.y; x[6]=v1.z; x[7]=v1.w;
    float ss = 0.f;
    #pragma unroll
    for (int i = 0; i < 8; i++) ss += x[i] * x[i];
    ss = warp_sum(ss);
    ss = __shfl_sync(0xFFFFFFFFu, ss, 0);
    float inv = 1.0f / fmaxf(sqrtf(ss), 1e-12f);
    __nv_bfloat16 hi[8], lo[8];
    #pragma unroll
    for (int i = 0; i < 8; i++) {
        float val = x[i] * inv;
        hi[i] = __float2bfloat16(val);
        lo[i] = __float2bfloat16(val - __bfloat162float(hi[i]));
    }
    size_t off = (size_t)gwarp * DDIM + lane * 8;
    *reinterpret_cast<uint4*>(&g_Ahi[off]) = *reinterpret_cast<uint4*>(hi);
    *reinterpret_cast<uint4*>(&g_Alo[off]) = *reinterpret_cast<uint4*>(lo);
}

// ---------------------------------------------------------------------------
// 2. Normalize head rows (dim=1), write TRANSPOSED hi/lo: Bt[n,d]=Hs[d,n]
// ---------------------------------------------------------------------------
__global__ __launch_bounds__(256) void k_prep_head(const float* __restrict__ head) {
    int d = blockIdx.x;
    const float* row = head + (size_t)d * KCLS;
    float ss = 0.f;
    for (int k = threadIdx.x; k < KCLS; k += 256) {
        float v = row[k];
        ss += v * v;
    }
    __shared__ float sred[8];
    ss = warp_sum(ss);
    if ((threadIdx.x & 31) == 0) sred[threadIdx.x >> 5] = ss;
    __syncthreads();
    if (threadIdx.x < 8) {
        float s = sred[threadIdx.x];
        #pragma unroll
        for (int o = 4; o > 0; o >>= 1) s += __shfl_down_sync(0xFFu, s, o);
        if (threadIdx.x == 0) sred[0] = 1.0f / fmaxf(sqrtf(s), 1e-12f);
    }
    __syncthreads();
    float inv = sred[0];
    for (int k = threadIdx.x; k < KCLS; k += 256) {
        float val = row[k] * inv;
        __nv_bfloat16 hi = __float2bfloat16(val);
        __nv_bfloat16 lo = __float2bfloat16(val - __bfloat162float(hi));
        g_Bhi[(size_t)k * DDIM + d] = hi;
        g_Blo[(size_t)k * DDIM + d] = lo;
    }
}

// ---------------------------------------------------------------------------
// 3. Zero accumulators (runs every launch; graph replayed)
// ---------------------------------------------------------------------------
__global__ void k_zero() {
    int t = blockIdx.x * blockDim.x + threadIdx.x;
    if (t < KPAD) g_u[t] = 0.f;
    if (t == 0)  g_S = 0.0;
}

// ---------------------------------------------------------------------------
// 4. HMMA GEMM + exp. 128x128 CTA tile; 8 warps (2m x 4n), 64x32 warp tile.
//    E = exp(20 * (Ahi+Alo)@(Bhi+Blo)^T) via 3 bf16 passes (hi.hi, hi.lo, lo.hi).
//    Epilogue: exp + direct float2 stores from fragments, col sums -> g_u, g_S.
// ---------------------------------------------------------------------------
#define SMEM_GEMM_TOTAL (65536 + 512)

__global__ __launch_bounds__(256, 2) void k_gemm_mma() {
    extern __shared__ char smem[];
    const uint32_t A_HI = 0, A_LO = 16384, B_HI = 32768, B_LO = 49152;
    float* scol = reinterpret_cast<float*>(smem + 65536);
    uint32_t sbase = smem_u32(smem);

    int tid = threadIdx.x, wid = tid >> 5, lane = tid & 31;
    int n0 = blockIdx.x * 128;
    int b0 = blockIdx.y * 128;
    int wm = (wid & 1) * 64;        // warp m offset
    int wn = (wid >> 1) * 32;       // warp n offset

    float acc[4][4][4];
    #pragma unroll
    for (int i = 0; i < 4; i++)
        #pragma unroll
        for (int j = 0; j < 4; j++)
            #pragma unroll
            for (int q = 0; q < 4; q++) acc[i][j][q] = 0.f;

    // ldmatrix lane address components (within a 128x64 bf16 tile, 128B rows)
    int a_row = (lane & 7) + ((lane >> 3) & 1) * 8;   // + mt*16 + wm
    int a_colb = (lane >> 4) * 16;                     // + ks*32
    int b_row = (lane & 7) + ((lane >> 4) & 1) * 8;   // + ntp*16 + wn  (x4 = 2 n-tiles)
    int b_colb = ((lane >> 3) & 1) * 16;               // + ks*32

    for (int c = 0; c < 4; c++) {
        // Stage 4 tiles of 128x64 bf16 (16KB each), SW128-swizzled
        #pragma unroll
        for (int i = 0; i < 4; i++) {
            int idx = tid + i * 256;           // uint4 slot 0..1023
            int row = idx >> 3;
            int c16 = idx & 7;
            uint32_t sw = SW128((uint32_t)(row * 128 + c16 * 16));
            size_t gA = (size_t)(b0 + row) * DDIM + c * 64 + c16 * 8;
            size_t gB = (size_t)(n0 + row) * DDIM + c * 64 + c16 * 8;
            *reinterpret_cast<uint4*>(smem + A_HI + sw) = *reinterpret_cast<const uint4*>(&g_Ahi[gA]);
            *reinterpret_cast<uint4*>(smem + A_LO + sw) = *reinterpret_cast<const uint4*>(&g_Alo[gA]);
            *reinterpret_cast<uint4*>(smem + B_HI + sw) = *reinterpret_cast<const uint4*>(&g_Bhi[gB]);
            *reinterpret_cast<uint4*>(smem + B_LO + sw) = *reinterpret_cast<const uint4*>(&g_Blo[gB]);
        }
        __syncthreads();

        #pragma unroll
        for (int ks = 0; ks < 4; ks++) {
            uint32_t a[4][4], bh[4][2], bl[4][2];
            // B hi + lo: 2 ldmatrix.x4 each (covers 2 n-tiles per ldsm)
            #pragma unroll
            for (int np = 0; np < 2; np++) {
                uint32_t off = (uint32_t)((wn + np * 16 + b_row) * 128 + ks * 32 + b_colb);
                uint32_t sw = SW128(off);
                ldsm_x4(bh[np*2][0], bh[np*2][1], bh[np*2+1][0], bh[np*2+1][1], sbase + B_HI + sw);
                ldsm_x4(bl[np*2][0], bl[np*2][1], bl[np*2+1][0], bl[np*2+1][1], sbase + B_LO + sw);
            }
            // A hi
            #pragma unroll
            for (int mt = 0; mt < 4; mt++) {
                uint32_t off = (uint32_t)((wm + mt * 16 + a_row) * 128 + ks * 32 + a_colb);
                uint32_t sw = SW128(off);
                ldsm_x4(a[mt][0], a[mt][1], a[mt][2], a[mt][3], sbase + A_HI + sw);
            }
            // hi*hi and hi*lo
            #pragma unroll
            for (int mt = 0; mt < 4; mt++)
                #pragma unroll
                for (int nt = 0; nt < 4; nt++) {
                    mma_bf16(acc[mt][nt], a[mt], bh[nt]);
                    mma_bf16(acc[mt][nt], a[mt], bl[nt]);
                }
            // A lo (overwrite), then lo*hi
            #pragma unroll
            for (int mt = 0; mt < 4; mt++) {
                uint32_t off = (uint32_t)((wm + mt * 16 + a_row) * 128 + ks * 32 + a_colb);
                uint32_t sw = SW128(off);
                ldsm_x4(a[mt][0], a[mt][1], a[mt][2], a[mt][3], sbase + A_LO + sw);
            }
            #pragma unroll
            for (int mt = 0; mt < 4; mt++)
                #pragma unroll
                for (int nt = 0; nt < 4; nt++)
                    mma_bf16(acc[mt][nt], a[mt], bh[nt]);
        }
        __syncthreads();
    }

    // ---- Epilogue: exp, direct stores, column sums ----
    if (tid < 128) scol[tid] = 0.f;
    __syncthreads();

    int g = lane >> 2;                 // fragment row group 0..7
    int t2 = (lane & 3) * 2;           // fragment col pair base
    float csum[4][2];
    #pragma unroll
    for (int nt = 0; nt < 4; nt++) { csum[nt][0] = 0.f; csum[nt][1] = 0.f; }

    #pragma unroll
    for (int mt = 0; mt < 4; mt++) {
        int r0 = b0 + wm + mt * 16 + g;
        #pragma unroll
        for (int nt = 0; nt < 4; nt++) {
            int col = n0 + wn + nt * 8 + t2;
            float2 e0, e1;
            e0.x = __expf(INV_EPS * acc[mt][nt][0]);
            e0.y = __expf(INV_EPS * acc[mt][nt][1]);
            e1.x = __expf(INV_EPS * acc[mt][nt][2]);
            e1.y = __expf(INV_EPS * acc[mt][nt][3]);
            *reinterpret_cast<float2*>(&g_E[(size_t)r0 * KPAD + col]) = e0;
            *reinterpret_cast<float2*>(&g_E[(size_t)(r0 + 8) * KPAD + col]) = e1;
            csum[nt][0] += e0.x + e1.x;
            csum[nt][1] += e0.y + e1.y;
        }
    }
    #pragma unroll
    for (int nt = 0; nt < 4; nt++) {
        atomicAdd(&scol[wn + nt * 8 + t2],     csum[nt][0]);
        atomicAdd(&scol[wn + nt * 8 + t2 + 1], csum[nt][1]);
    }
    __syncthreads();

    if (tid < 128) atomicAdd(&g_u[n0 + tid], scol[tid]);  // pads land in g_u[1000..1023]
    if (tid < 32) {
        float s = 0.f;
        #pragma unroll
        for (int i = 0; i < 4; i++) {
            int k = tid + i * 32;
            if (n0 + k < KCLS) s += scol[k];
        }
        s = warp_sum(s);
        if (tid == 0) atomicAdd(&g_S, (double)s);
    }
}

// ---------------------------------------------------------------------------
// 5. r_k = S / (K * u_k) for k<1000, 0 for pads; reset u.
// ---------------------------------------------------------------------------
__global__ void k_fin_r() {
    int k = blockIdx.x * blockDim.x + threadIdx.x;
    if (k < KPAD) {
        if (k < KCLS) {
            double u = (double)g_u[k];
            g_r[k] = (float)(g_S / ((double)KCLS * u));
        } else {
            g_r[k] = 0.f;
        }
        g_u[k] = 0.f;
    }
}

// ---------------------------------------------------------------------------
// 6. Row reduce: v_b = sum_k E[b,k]*r_k ; c_b = S/(B*v_b). One warp per row.
// ---------------------------------------------------------------------------
__global__ __launch_bounds__(256) void k_v_c() {
    __shared__ __align__(16) float rsh[KPAD];
    for (int k = threadIdx.x; k < KPAD; k += 256) rsh[k] = g_r[k];
    __syncthreads();
    int warp = threadIdx.x >> 5;
    int lane = threadIdx.x & 31;
    int b = blockIdx.x * 8 + warp;
    const float4* E4 = reinterpret_cast<const float4*>(g_E + (size_t)b * KPAD);
    const float4* r4 = reinterpret_cast<const float4*>(rsh);
    float v = 0.f;
    #pragma unroll
    for (int i = 0; i < 8; i++) {
        int idx = lane + i * 32;       // 0..255 all valid (1024/4)
        float4 e = E4[idx];
        float4 r = r4[idx];
        v += e.x * r.x + e.y * r.y + e.z * r.z + e.w * r.w;
    }
    v = warp_sum(v);
    if (lane == 0) g_c[b] = (float)(g_S / ((double)B_TOT * (double)v));
}

// ---------------------------------------------------------------------------
// 7. Column reduce: u_k += sum_{b in chunk} E[b,k]*c_b. float4 per thread.
// ---------------------------------------------------------------------------
#define UCHUNK 64
__global__ __launch_bounds__(256) void k_u_pass() {
    __shared__ float csh[UCHUNK];
    int c4 = threadIdx.x;                  // float4 column group 0..255
    int b0 = blockIdx.y * UCHUNK;
    if (threadIdx.x < UCHUNK) csh[threadIdx.x] = g_c[b0 + threadIdx.x];
    __syncthreads();
    const float4* E4 = reinterpret_cast<const float4*>(g_E);
    float4 acc = make_float4(0.f, 0.f, 0.f, 0.f);
    #pragma unroll 8
    for (int i = 0; i < UCHUNK; i++) {
        float cb = csh[i];
        float4 e = E4[(size_t)(b0 + i) * (KPAD / 4) + c4];
        acc.x += e.x * cb; acc.y += e.y * cb; acc.z += e.z * cb; acc.w += e.w * cb;
    }
    atomicAdd(&g_u[c4 * 4 + 0], acc.x);
    atomicAdd(&g_u[c4 * 4 + 1], acc.y);
    atomicAdd(&g_u[c4 * 4 + 2], acc.z);
    atomicAdd(&g_u[c4 * 4 + 3], acc.w);
}

// ---------------------------------------------------------------------------
// 8. Output: out[b,k] = (B/S) * r_k * c_b * E[b,k], b < 4096, k < 1000
// ---------------------------------------------------------------------------
__global__ __launch_bounds__(256) void k_out(float* __restrict__ out) {
    int idx = blockIdx.x * 256 + threadIdx.x;           // float4 index in output
    const int TOT4 = N_OUT * (KCLS / 4);
    if (idx >= TOT4) return;
    int b  = idx / (KCLS / 4);
    int k4 = idx - b * (KCLS / 4);
    float s = (float)((double)B_TOT / g_S) * g_c[b];
    float4 e = reinterpret_cast<const float4*>(g_E)[(size_t)b * (KPAD / 4) + k4];
    float4 r = reinterpret_cast<const float4*>(g_r)[k4];
    float4 o;
    o.x = s * r.x * e.x;
    o.y = s * r.y * e.y;
    o.z = s * r.z * e.z;
    o.w = s * r.w * e.w;
    reinterpret_cast<float4*>(out)[idx] = o;
}

// ---------------------------------------------------------------------------
extern "C" void kernel_launch(void* const* d_in, const int* in_sizes, int n_in,
                              void* d_out, int out_size) {
    const float* features = (const float*)d_in[0];
    const float* head     = (const float*)d_in[1];
    const float* queue    = (const float*)d_in[2];
    float* out = (float*)d_out;

    cudaFuncSetAttribute(k_gemm_mma, cudaFuncAttributeMaxDynamicSharedMemorySize,
                         SMEM_GEMM_TOTAL);

    k_prep_feat<<<(B_TOT * 32) / 256, 256>>>(features, queue);
    k_prep_head<<<DDIM, 256>>>(head);
    k_zero<<<4, 256>>>();
    k_gemm_mma<<<dim3(KPAD / 128, B_TOT / 128), 256, SMEM_GEMM_TOTAL>>>();
    // iter 1
    k_fin_r<<<4, 256>>>();
    k_v_c<<<B_TOT / 8, 256>>>();
    // iter 2
    k_u_pass<<<dim3(1, B_TOT / UCHUNK), 256>>>();
    k_fin_r<<<4, 256>>>();
    k_v_c<<<B_TOT / 8, 256>>>();
    // iter 3
    k_u_pass<<<dim3(1, B_TOT / UCHUNK), 256>>>();
    k_fin_r<<<4, 256>>>();
    k_v_c<<<B_TOT / 8, 256>>>();
    // output
    k_out<<<(N_OUT * (KCLS / 4) + 255) / 256, 256>>>(out);
}

// round 5
// speedup vs baseline: 1.9486x; 1.2761x over previous
#include <cuda_runtime.h>
#include <cuda_bf16.h>
#include <cstdint>

// Problem constants
#define B_TOT 12288   // features(4096) + queue(8192)
#define N_OUT 4096
#define KCLS  1000
#define KPAD  1024
#define DDIM  256
#define INV_EPS 20.0f

// ---------------------------------------------------------------------------
// Device scratch (allocation-free)
// ---------------------------------------------------------------------------
__device__ float           g_E[B_TOT * KPAD];     // exp(logits/eps), [b, 1024] (50 MB)
__device__ __nv_bfloat16   g_Ahi[B_TOT * DDIM];   // normalized features, hi
__device__ __nv_bfloat16   g_Alo[B_TOT * DDIM];   // normalized features, lo
__device__ __nv_bfloat16   g_Bhi[KPAD * DDIM];    // normalized head^T, hi (pad rows stay 0)
__device__ __nv_bfloat16   g_Blo[KPAD * DDIM];    // normalized head^T, lo
__device__ float           g_u[KPAD];
__device__ float           g_r[KPAD];
__device__ double          g_S;

__device__ __forceinline__ float warp_sum(float v) {
    #pragma unroll
    for (int o = 16; o > 0; o >>= 1) v += __shfl_down_sync(0xFFFFFFFFu, v, o);
    return v;
}

__device__ __forceinline__ uint32_t smem_u32(const void* p) {
    uint32_t a;
    asm("{ .reg .u64 t; cvta.to.shared.u64 t, %1; cvt.u32.u64 %0, t; }" : "=r"(a) : "l"(p));
    return a;
}

#define SW64(o) ((o) ^ (((o) >> 3) & 0x30))

__device__ __forceinline__ void ldsm_x4(uint32_t& r0, uint32_t& r1, uint32_t& r2, uint32_t& r3,
                                        uint32_t addr) {
    asm volatile("ldmatrix.sync.aligned.m8n8.x4.shared.b16 {%0,%1,%2,%3}, [%4];"
                 : "=r"(r0), "=r"(r1), "=r"(r2), "=r"(r3) : "r"(addr));
}

__device__ __forceinline__ void mma_bf16(float* d, const uint32_t* a, const uint32_t* b) {
    asm volatile(
        "mma.sync.aligned.m16n8k16.row.col.f32.bf16.bf16.f32 "
        "{%0,%1,%2,%3}, {%4,%5,%6,%7}, {%8,%9}, {%0,%1,%2,%3};"
        : "+f"(d[0]), "+f"(d[1]), "+f"(d[2]), "+f"(d[3])
        : "r"(a[0]), "r"(a[1]), "r"(a[2]), "r"(a[3]), "r"(b[0]), "r"(b[1]));
}

__device__ __forceinline__ void cp_async16(uint32_t dst, const void* src) {
    asm volatile("cp.async.cg.shared.global [%0], [%1], 16;" :: "r"(dst), "l"(src));
}
__device__ __forceinline__ void cp_commit() {
    asm volatile("cp.async.commit_group;" ::: "memory");
}
template <int N> __device__ __forceinline__ void cp_wait() {
    asm volatile("cp.async.wait_group %0;" :: "n"(N) : "memory");
}

// ---------------------------------------------------------------------------
// 1. Normalize feature rows; split into bf16 hi/lo. One warp per row.
// ---------------------------------------------------------------------------
__global__ __launch_bounds__(256) void k_prep_feat(const float* __restrict__ features,
                                                   const float* __restrict__ queue) {
    int gwarp = (blockIdx.x * blockDim.x + threadIdx.x) >> 5;
    int lane  = threadIdx.x & 31;
    if (gwarp >= B_TOT) return;
    const float* row = (gwarp < N_OUT) ? (features + (size_t)gwarp * DDIM)
                                       : (queue + (size_t)(gwarp - N_OUT) * DDIM);
    float x[8];
    const float4* r4 = reinterpret_cast<const float4*>(row + lane * 8);
    float4 v0 = r4[0], v1 = r4[1];
    x[0]=v0.x; x[1]=v0.y; x[2]=v0.z; x[3]=v0.w;
    x[4]=v1.x; x[5]=v1.y; x[6]=v1.z; x[7]=v1.w;
    float ss = 0.f;
    #pragma unroll
    for (int i = 0; i < 8; i++) ss += x[i] * x[i];
    ss = warp_sum(ss);
    ss = __shfl_sync(0xFFFFFFFFu, ss, 0);
    float inv = 1.0f / fmaxf(sqrtf(ss), 1e-12f);
    __nv_bfloat16 hi[8], lo[8];
    #pragma unroll
    for (int i = 0; i < 8; i++) {
        float val = x[i] * inv;
        hi[i] = __float2bfloat16(val);
        lo[i] = __float2bfloat16(val - __bfloat162float(hi[i]));
    }
    size_t off = (size_t)gwarp * DDIM + lane * 8;
    *reinterpret_cast<uint4*>(&g_Ahi[off]) = *reinterpret_cast<uint4*>(hi);
    *reinterpret_cast<uint4*>(&g_Alo[off]) = *reinterpret_cast<uint4*>(lo);
}

// ---------------------------------------------------------------------------
// 2. Normalize head rows (dim=1), write TRANSPOSED hi/lo: Bt[n,d]=Hs[d,n]
// ---------------------------------------------------------------------------
__global__ __launch_bounds__(256) void k_prep_head(const float* __restrict__ head) {
    int d = blockIdx.x;
    const float* row = head + (size_t)d * KCLS;
    float ss = 0.f;
    for (int k = threadIdx.x; k < KCLS; k += 256) {
        float v = row[k];
        ss += v * v;
    }
    __shared__ float sred[8];
    ss = warp_sum(ss);
    if ((threadIdx.x & 31) == 0) sred[threadIdx.x >> 5] = ss;
    __syncthreads();
    if (threadIdx.x < 8) {
        float s = sred[threadIdx.x];
        #pragma unroll
        for (int o = 4; o > 0; o >>= 1) s += __shfl_down_sync(0xFFu, s, o);
        if (threadIdx.x == 0) sred[0] = 1.0f / fmaxf(sqrtf(s), 1e-12f);
    }
    __syncthreads();
    float inv = sred[0];
    for (int k = threadIdx.x; k < KCLS; k += 256) {
        float val = row[k] * inv;
        __nv_bfloat16 hi = __float2bfloat16(val);
        __nv_bfloat16 lo = __float2bfloat16(val - __bfloat162float(hi));
        g_Bhi[(size_t)k * DDIM + d] = hi;
        g_Blo[(size_t)k * DDIM + d] = lo;
    }
}

// ---------------------------------------------------------------------------
// 3. Zero accumulators (runs every launch; graph replayed)
// ---------------------------------------------------------------------------
__global__ void k_zero() {
    int t = blockIdx.x * blockDim.x + threadIdx.x;
    if (t < KPAD) g_u[t] = 0.f;
    if (t == 0)  g_S = 0.0;
}

// ---------------------------------------------------------------------------
// 4. HMMA GEMM + exp with 3-stage cp.async pipeline.
//    128x128 CTA tile; 8 warps (2m x 4n); K in 8 chunks of 32.
//    E = exp(20 * (Ahi+Alo)@(Bhi+Blo)^T) via 3 bf16 passes.
// ---------------------------------------------------------------------------
#define CH 32
#define NCH 8
#define TILE_BYTES 8192                   // 128 rows x 64B
#define STAGE_BYTES (4 * TILE_BYTES)      // Ahi, Alo, Bhi, Blo
#define NSTAGE 3
#define SMEM_GEMM_TOTAL (NSTAGE * STAGE_BYTES + 512)

__device__ __forceinline__ void load_stage(uint32_t sbase, int buf, int b0, int n0,
                                           int c, int tid) {
    uint32_t dstb = sbase + (uint32_t)buf * STAGE_BYTES;
    #pragma unroll
    for (int j = 0; j < 2; j++) {
        int slot = tid + j * 256;          // 0..511
        int row  = slot >> 2;
        int c16  = slot & 3;
        uint32_t sw = SW64((uint32_t)(row * 64 + c16 * 16));
        size_t gA = (size_t)(b0 + row) * DDIM + c * CH + c16 * 8;
        size_t gB = (size_t)(n0 + row) * DDIM + c * CH + c16 * 8;
        cp_async16(dstb + 0 * TILE_BYTES + sw, &g_Ahi[gA]);
        cp_async16(dstb + 1 * TILE_BYTES + sw, &g_Alo[gA]);
        cp_async16(dstb + 2 * TILE_BYTES + sw, &g_Bhi[gB]);
        cp_async16(dstb + 3 * TILE_BYTES + sw, &g_Blo[gB]);
    }
}

__global__ __launch_bounds__(256, 2) void k_gemm_mma() {
    extern __shared__ char smem[];
    float* scol = reinterpret_cast<float*>(smem + NSTAGE * STAGE_BYTES);
    uint32_t sbase = smem_u32(smem);

    int tid = threadIdx.x, wid = tid >> 5, lane = tid & 31;
    int n0 = blockIdx.x * 128;
    int b0 = blockIdx.y * 128;
    int wm = (wid & 1) * 64;
    int wn = (wid >> 1) * 32;

    float acc[4][4][4];
    #pragma unroll
    for (int i = 0; i < 4; i++)
        #pragma unroll
        for (int j = 0; j < 4; j++)
            #pragma unroll
            for (int q = 0; q < 4; q++) acc[i][j][q] = 0.f;

    int a_row  = (lane & 7) + ((lane >> 3) & 1) * 8;
    int a_colb = (lane >> 4) * 16;
    int b_row  = (lane & 7) + ((lane >> 4) & 1) * 8;
    int b_colb = ((lane >> 3) & 1) * 16;

    // Pipeline prologue: stages 0..2
    #pragma unroll
    for (int s = 0; s < NSTAGE; s++) { load_stage(sbase, s, b0, n0, s, tid); cp_commit(); }

    for (int c = 0; c < NCH; c++) {
        cp_wait<NSTAGE - 1>();
        __syncthreads();
        uint32_t tb = sbase + (uint32_t)(c % NSTAGE) * STAGE_BYTES;

        #pragma unroll
        for (int ks = 0; ks < 2; ks++) {
            uint32_t a[4][4], bh[4][2], bl[4][2];
            #pragma unroll
            for (int np = 0; np < 2; np++) {
                uint32_t sw = SW64((uint32_t)((wn + np * 16 + b_row) * 64 + ks * 32 + b_colb));
                ldsm_x4(bh[np*2][0], bh[np*2][1], bh[np*2+1][0], bh[np*2+1][1],
                        tb + 2 * TILE_BYTES + sw);
                ldsm_x4(bl[np*2][0], bl[np*2][1], bl[np*2+1][0], bl[np*2+1][1],
                        tb + 3 * TILE_BYTES + sw);
            }
            #pragma unroll
            for (int mt = 0; mt < 4; mt++) {
                uint32_t sw = SW64((uint32_t)((wm + mt * 16 + a_row) * 64 + ks * 32 + a_colb));
                ldsm_x4(a[mt][0], a[mt][1], a[mt][2], a[mt][3], tb + 0 * TILE_BYTES + sw);
            }
            #pragma unroll
            for (int mt = 0; mt < 4; mt++)
                #pragma unroll
                for (int nt = 0; nt < 4; nt++) {
                    mma_bf16(acc[mt][nt], a[mt], bh[nt]);
                    mma_bf16(acc[mt][nt], a[mt], bl[nt]);
                }
            #pragma unroll
            for (int mt = 0; mt < 4; mt++) {
                uint32_t sw = SW64((uint32_t)((wm + mt * 16 + a_row) * 64 + ks * 32 + a_colb));
                ldsm_x4(a[mt][0], a[mt][1], a[mt][2], a[mt][3], tb + 1 * TILE_BYTES + sw);
            }
            #pragma unroll
            for (int mt = 0; mt < 4; mt++)
                #pragma unroll
                for (int nt = 0; nt < 4; nt++)
                    mma_bf16(acc[mt][nt], a[mt], bh[nt]);
        }
        __syncthreads();
        if (c + NSTAGE < NCH) load_stage(sbase, c % NSTAGE, b0, n0, c + NSTAGE, tid);
        cp_commit();
    }

    // ---- Epilogue: exp, direct stores, column sums ----
    if (tid < 128) scol[tid] = 0.f;
    __syncthreads();

    int g = lane >> 2;
    int t2 = (lane & 3) * 2;
    float csum[4][2];
    #pragma unroll
    for (int nt = 0; nt < 4; nt++) { csum[nt][0] = 0.f; csum[nt][1] = 0.f; }

    #pragma unroll
    for (int mt = 0; mt < 4; mt++) {
        int r0 = b0 + wm + mt * 16 + g;
        #pragma unroll
        for (int nt = 0; nt < 4; nt++) {
            int col = n0 + wn + nt * 8 + t2;
            float2 e0, e1;
            e0.x = __expf(INV_EPS * acc[mt][nt][0]);
            e0.y = __expf(INV_EPS * acc[mt][nt][1]);
            e1.x = __expf(INV_EPS * acc[mt][nt][2]);
            e1.y = __expf(INV_EPS * acc[mt][nt][3]);
            *reinterpret_cast<float2*>(&g_E[(size_t)r0 * KPAD + col]) = e0;
            *reinterpret_cast<float2*>(&g_E[(size_t)(r0 + 8) * KPAD + col]) = e1;
            csum[nt][0] += e0.x + e1.x;
            csum[nt][1] += e0.y + e1.y;
        }
    }
    #pragma unroll
    for (int nt = 0; nt < 4; nt++) {
        atomicAdd(&scol[wn + nt * 8 + t2],     csum[nt][0]);
        atomicAdd(&scol[wn + nt * 8 + t2 + 1], csum[nt][1]);
    }
    __syncthreads();

    if (tid < 128) atomicAdd(&g_u[n0 + tid], scol[tid]);  // pads land in g_u[1000..1023]
    if (tid < 32) {
        float s = 0.f;
        #pragma unroll
        for (int i = 0; i < 4; i++) {
            int k = tid + i * 32;
            if (n0 + k < KCLS) s += scol[k];
        }
        s = warp_sum(s);
        if (tid == 0) atomicAdd(&g_S, (double)s);
    }
}

// ---------------------------------------------------------------------------
// 5. r_k = S / (K * u_k) for k<1000, 0 for pads; reset u.
// ---------------------------------------------------------------------------
__global__ void k_fin_r() {
    int k = blockIdx.x * blockDim.x + threadIdx.x;
    if (k < KPAD) {
        if (k < KCLS) {
            double u = (double)g_u[k];
            g_r[k] = (float)(g_S / ((double)KCLS * u));
        } else {
            g_r[k] = 0.f;
        }
        g_u[k] = 0.f;
    }
}

// ---------------------------------------------------------------------------
// 6. Fused pass: per row b compute v_b = E[b,:].r, c_b = S/(B v_b), and
//    accumulate u_k += E[b,k] * c_b. One warp per row; per-lane register
//    accumulators over fixed columns; smem combine; one atomic flush.
//    128 blocks x 8 warps x 12 rows = 12288.
// ---------------------------------------------------------------------------
__global__ __launch_bounds__(256) void k_vcu() {
    __shared__ __align__(16) float rsh[KPAD];
    __shared__ float ush[KPAD];
    for (int k = threadIdx.x; k < KPAD; k += 256) { rsh[k] = g_r[k]; ush[k] = 0.f; }
    __syncthreads();

    int warp = threadIdx.x >> 5, lane = threadIdx.x & 31;
    double Sd = g_S;
    const float4* r4 = reinterpret_cast<const float4*>(rsh);

    float uacc[32];
    #pragma unroll
    for (int i = 0; i < 32; i++) uacc[i] = 0.f;

    #pragma unroll 1
    for (int it = 0; it < 12; it++) {
        int b = blockIdx.x * 96 + warp * 12 + it;
        const float4* E4 = reinterpret_cast<const float4*>(g_E + (size_t)b * KPAD);
        float4 e[8];
        float v = 0.f;
        #pragma unroll
        for (int i = 0; i < 8; i++) {
            e[i] = E4[lane + i * 32];
            float4 r = r4[lane + i * 32];
            v += e[i].x * r.x + e[i].y * r.y + e[i].z * r.z + e[i].w * r.w;
        }
        v = warp_sum(v);
        v = __shfl_sync(0xFFFFFFFFu, v, 0);
        float cb = (float)(Sd / ((double)B_TOT * (double)v));
        #pragma unroll
        for (int i = 0; i < 8; i++) {
            uacc[i * 4 + 0] += e[i].x * cb;
            uacc[i * 4 + 1] += e[i].y * cb;
            uacc[i * 4 + 2] += e[i].z * cb;
            uacc[i * 4 + 3] += e[i].w * cb;
        }
    }
    #pragma unroll
    for (int i = 0; i < 8; i++) {
        int k0 = 4 * (lane + i * 32);
        atomicAdd(&ush[k0 + 0], uacc[i * 4 + 0]);
        atomicAdd(&ush[k0 + 1], uacc[i * 4 + 1]);
        atomicAdd(&ush[k0 + 2], uacc[i * 4 + 2]);
        atomicAdd(&ush[k0 + 3], uacc[i * 4 + 3]);
    }
    __syncthreads();
    for (int k = threadIdx.x; k < KPAD; k += 256) atomicAdd(&g_u[k], ush[k]);
}

// ---------------------------------------------------------------------------
// 7. Final fused pass (rows 0..4095 only):
//    v_b = E[b,:].r3 ; out[b,k] = E[b,k] * r3_k / v_b
//    64 blocks x 8 warps x 8 rows = 4096.
// ---------------------------------------------------------------------------
__global__ __launch_bounds__(256) void k_final(float* __restrict__ out) {
    __shared__ __align__(16) float rsh[KPAD];
    for (int k = threadIdx.x; k < KPAD; k += 256) rsh[k] = g_r[k];
    __syncthreads();
    int warp = threadIdx.x >> 5, lane = threadIdx.x & 31;
    const float4* r4 = reinterpret_cast<const float4*>(rsh);

    #pragma unroll 1
    for (int it = 0; it < 8; it++) {
        int b = blockIdx.x * 64 + warp * 8 + it;
        const float4* E4 = reinterpret_cast<const float4*>(g_E + (size_t)b * KPAD);
        float4 e[8];
        float v = 0.f;
        #pragma unroll
        for (int i = 0; i < 8; i++) {
            e[i] = E4[lane + i * 32];
            float4 r = r4[lane + i * 32];
            v += e[i].x * r.x + e[i].y * r.y + e[i].z * r.z + e[i].w * r.w;
        }
        v = warp_sum(v);
        v = __shfl_sync(0xFFFFFFFFu, v, 0);
        float invv = 1.0f / v;
        float* orow = out + (size_t)b * KCLS;       // b*1000*4B is 16B aligned (4000*b)
        #pragma unroll
        for (int i = 0; i < 8; i++) {
            int idx = lane + i * 32;                 // float4 index, valid < 250
            if (idx < KCLS / 4) {
                float4 r = r4[idx];
                float4 o;
                o.x = e[i].x * r.x * invv;
                o.y = e[i].y * r.y * invv;
                o.z = e[i].z * r.z * invv;
                o.w = e[i].w * r.w * invv;
                *reinterpret_cast<float4*>(orow + idx * 4) = o;
            }
        }
    }
}

// ---------------------------------------------------------------------------
extern "C" void kernel_launch(void* const* d_in, const int* in_sizes, int n_in,
                              void* d_out, int out_size) {
    const float* features = (const float*)d_in[0];
    const float* head     = (const float*)d_in[1];
    const float* queue    = (const float*)d_in[2];
    float* out = (float*)d_out;

    cudaFuncSetAttribute(k_gemm_mma, cudaFuncAttributeMaxDynamicSharedMemorySize,
                         SMEM_GEMM_TOTAL);

    k_prep_feat<<<(B_TOT * 32) / 256, 256>>>(features, queue);
    k_prep_head<<<DDIM, 256>>>(head);
    k_zero<<<4, 256>>>();
    k_gemm_mma<<<dim3(KPAD / 128, B_TOT / 128), 256, SMEM_GEMM_TOTAL>>>();
    // iter 1: row-normalize (r1), then fused col-normalize + next col-sum
    k_fin_r<<<4, 256>>>();
    k_vcu<<<128, 256>>>();
    // iter 2
    k_fin_r<<<4, 256>>>();
    k_vcu<<<128, 256>>>();
    // iter 3: r3, then fused final col-normalize + output (rows < 4096 only)
    k_fin_r<<<4, 256>>>();
    k_final<<<64, 256>>>(out);
}

// round 6
// speedup vs baseline: 1.9876x; 1.0200x over previous
#include <cuda_runtime.h>
#include <cuda_fp16.h>
#include <cstdint>

// Problem constants
#define B_TOT 12288   // features(4096) + queue(8192)
#define N_OUT 4096
#define KCLS  1000
#define KPAD  1024
#define DDIM  256
#define INV_EPS 20.0f

// ---------------------------------------------------------------------------
// Device scratch (allocation-free)
// ---------------------------------------------------------------------------
__device__ float   g_E[B_TOT * KPAD];   // exp(logits/eps), [b, 1024] (50 MB)
__device__ __half  g_Ah[B_TOT * DDIM];  // normalized features, fp16
__device__ __half  g_Bh[KPAD * DDIM];   // normalized head^T, fp16 (pad rows stay 0)
__device__ float   g_u[KPAD];
__device__ float   g_r[KPAD];
__device__ double  g_S;
__device__ int     g_cnt;               // last-block ticket (self-resetting)

__device__ __forceinline__ float warp_sum(float v) {
    #pragma unroll
    for (int o = 16; o > 0; o >>= 1) v += __shfl_down_sync(0xFFFFFFFFu, v, o);
    return v;
}

__device__ __forceinline__ uint32_t smem_u32(const void* p) {
    uint32_t a;
    asm("{ .reg .u64 t; cvta.to.shared.u64 t, %1; cvt.u32.u64 %0, t; }" : "=r"(a) : "l"(p));
    return a;
}

#define SW64(o) ((o) ^ (((o) >> 3) & 0x30))

__device__ __forceinline__ void ldsm_x4(uint32_t& r0, uint32_t& r1, uint32_t& r2, uint32_t& r3,
                                        uint32_t addr) {
    asm volatile("ldmatrix.sync.aligned.m8n8.x4.shared.b16 {%0,%1,%2,%3}, [%4];"
                 : "=r"(r0), "=r"(r1), "=r"(r2), "=r"(r3) : "r"(addr));
}

__device__ __forceinline__ void mma_f16(float* d, const uint32_t* a, const uint32_t* b) {
    asm volatile(
        "mma.sync.aligned.m16n8k16.row.col.f32.f16.f16.f32 "
        "{%0,%1,%2,%3}, {%4,%5,%6,%7}, {%8,%9}, {%0,%1,%2,%3};"
        : "+f"(d[0]), "+f"(d[1]), "+f"(d[2]), "+f"(d[3])
        : "r"(a[0]), "r"(a[1]), "r"(a[2]), "r"(a[3]), "r"(b[0]), "r"(b[1]));
}

__device__ __forceinline__ void cp_async16(uint32_t dst, const void* src) {
    asm volatile("cp.async.cg.shared.global [%0], [%1], 16;" :: "r"(dst), "l"(src));
}
__device__ __forceinline__ void cp_commit() {
    asm volatile("cp.async.commit_group;" ::: "memory");
}
template <int N> __device__ __forceinline__ void cp_wait() {
    asm volatile("cp.async.wait_group %0;" :: "n"(N) : "memory");
}

// Shared helper: compute r from (S, u), zero u, reset ticket. Call from the
// LAST block of a kernel (all threads of that block).
__device__ __forceinline__ void finalize_r(int tid) {
    double S = g_S;
    for (int k = tid; k < KPAD; k += 256) {
        float u;
        asm volatile("ld.global.cg.f32 %0, [%1];" : "=f"(u) : "l"(&g_u[k]));
        g_r[k] = (k < KCLS) ? (float)(S / ((double)KCLS * (double)u)) : 0.f;
        g_u[k] = 0.f;
    }
    if (tid == 0) g_cnt = 0;
}

// ---------------------------------------------------------------------------
// 1. Normalize feature rows -> fp16. One warp per row. Block 0 zeroes g_S.
// ---------------------------------------------------------------------------
__global__ __launch_bounds__(256) void k_prep_feat(const float* __restrict__ features,
                                                   const float* __restrict__ queue) {
    if (blockIdx.x == 0 && threadIdx.x == 0) g_S = 0.0;
    int gwarp = (blockIdx.x * blockDim.x + threadIdx.x) >> 5;
    int lane  = threadIdx.x & 31;
    if (gwarp >= B_TOT) return;
    const float* row = (gwarp < N_OUT) ? (features + (size_t)gwarp * DDIM)
                                       : (queue + (size_t)(gwarp - N_OUT) * DDIM);
    float x[8];
    const float4* r4 = reinterpret_cast<const float4*>(row + lane * 8);
    float4 v0 = r4[0], v1 = r4[1];
    x[0]=v0.x; x[1]=v0.y; x[2]=v0.z; x[3]=v0.w;
    x[4]=v1.x; x[5]=v1.y; x[6]=v1.z; x[7]=v1.w;
    float ss = 0.f;
    #pragma unroll
    for (int i = 0; i < 8; i++) ss += x[i] * x[i];
    ss = warp_sum(ss);
    ss = __shfl_sync(0xFFFFFFFFu, ss, 0);
    float inv = 1.0f / fmaxf(sqrtf(ss), 1e-12f);
    __half h[8];
    #pragma unroll
    for (int i = 0; i < 8; i++) h[i] = __float2half(x[i] * inv);
    *reinterpret_cast<uint4*>(&g_Ah[(size_t)gwarp * DDIM + lane * 8]) =
        *reinterpret_cast<uint4*>(h);
}

// ---------------------------------------------------------------------------
// 2. Normalize head rows (dim=1), write TRANSPOSED fp16: Bh[n,d]=Hs[d,n]
// ---------------------------------------------------------------------------
__global__ __launch_bounds__(256) void k_prep_head(const float* __restrict__ head) {
    int d = blockIdx.x;
    const float* row = head + (size_t)d * KCLS;
    float ss = 0.f;
    for (int k = threadIdx.x; k < KCLS; k += 256) {
        float v = row[k];
        ss += v * v;
    }
    __shared__ float sred[8];
    ss = warp_sum(ss);
    if ((threadIdx.x & 31) == 0) sred[threadIdx.x >> 5] = ss;
    __syncthreads();
    if (threadIdx.x < 8) {
        float s = sred[threadIdx.x];
        #pragma unroll
        for (int o = 4; o > 0; o >>= 1) s += __shfl_down_sync(0xFFu, s, o);
        if (threadIdx.x == 0) sred[0] = 1.0f / fmaxf(sqrtf(s), 1e-12f);
    }
    __syncthreads();
    float inv = sred[0];
    for (int k = threadIdx.x; k < KCLS; k += 256)
        g_Bh[(size_t)k * DDIM + d] = __float2half(row[k] * inv);
}

// ---------------------------------------------------------------------------
// 3. HMMA GEMM + exp, single fp16 pass, 3-stage cp.async pipeline.
//    128x128 CTA tile; 8 warps (2m x 4n); K in 8 chunks of 32.
//    Last block computes r1 from (S, u0) and zeroes u.
// ---------------------------------------------------------------------------
#define CH 32
#define NCH 8
#define TILE_BYTES 8192                   // 128 rows x 64B
#define STAGE_BYTES (2 * TILE_BYTES)      // A, B
#define NSTAGE 3
#define SMEM_GEMM_TOTAL (NSTAGE * STAGE_BYTES + 512)
#define GEMM_GRID (8 * 96)

__device__ __forceinline__ void load_stage(uint32_t sbase, int buf, int b0, int n0,
                                           int c, int tid) {
    uint32_t dstb = sbase + (uint32_t)buf * STAGE_BYTES;
    #pragma unroll
    for (int j = 0; j < 2; j++) {
        int slot = tid + j * 256;          // 0..511
        int row  = slot >> 2;
        int c16  = slot & 3;
        uint32_t sw = SW64((uint32_t)(row * 64 + c16 * 16));
        size_t gA = (size_t)(b0 + row) * DDIM + c * CH + c16 * 8;
        size_t gB = (size_t)(n0 + row) * DDIM + c * CH + c16 * 8;
        cp_async16(dstb + 0 * TILE_BYTES + sw, &g_Ah[gA]);
        cp_async16(dstb + 1 * TILE_BYTES + sw, &g_Bh[gB]);
    }
}

__global__ __launch_bounds__(256, 2) void k_gemm_mma() {
    extern __shared__ char smem[];
    float* scol = reinterpret_cast<float*>(smem + NSTAGE * STAGE_BYTES);
    __shared__ int sLast;
    uint32_t sbase = smem_u32(smem);

    int tid = threadIdx.x, wid = tid >> 5, lane = tid & 31;
    int n0 = blockIdx.x * 128;
    int b0 = blockIdx.y * 128;
    int wm = (wid & 1) * 64;
    int wn = (wid >> 1) * 32;

    float acc[4][4][4];
    #pragma unroll
    for (int i = 0; i < 4; i++)
        #pragma unroll
        for (int j = 0; j < 4; j++)
            #pragma unroll
            for (int q = 0; q < 4; q++) acc[i][j][q] = 0.f;

    int a_row  = (lane & 7) + ((lane >> 3) & 1) * 8;
    int a_colb = (lane >> 4) * 16;
    int b_row  = (lane & 7) + ((lane >> 4) & 1) * 8;
    int b_colb = ((lane >> 3) & 1) * 16;

    #pragma unroll
    for (int s = 0; s < NSTAGE; s++) { load_stage(sbase, s, b0, n0, s, tid); cp_commit(); }

    for (int c = 0; c < NCH; c++) {
        cp_wait<NSTAGE - 1>();
        __syncthreads();
        uint32_t tb = sbase + (uint32_t)(c % NSTAGE) * STAGE_BYTES;

        #pragma unroll
        for (int ks = 0; ks < 2; ks++) {
            uint32_t a[4][4], bh[4][2];
            #pragma unroll
            for (int np = 0; np < 2; np++) {
                uint32_t sw = SW64((uint32_t)((wn + np * 16 + b_row) * 64 + ks * 32 + b_colb));
                ldsm_x4(bh[np*2][0], bh[np*2][1], bh[np*2+1][0], bh[np*2+1][1],
                        tb + 1 * TILE_BYTES + sw);
            }
            #pragma unroll
            for (int mt = 0; mt < 4; mt++) {
                uint32_t sw = SW64((uint32_t)((wm + mt * 16 + a_row) * 64 + ks * 32 + a_colb));
                ldsm_x4(a[mt][0], a[mt][1], a[mt][2], a[mt][3], tb + 0 * TILE_BYTES + sw);
            }
            #pragma unroll
            for (int mt = 0; mt < 4; mt++)
                #pragma unroll
                for (int nt = 0; nt < 4; nt++)
                    mma_f16(acc[mt][nt], a[mt], bh[nt]);
        }
        __syncthreads();
        if (c + NSTAGE < NCH) load_stage(sbase, c % NSTAGE, b0, n0, c + NSTAGE, tid);
        cp_commit();
    }

    // ---- Epilogue: exp, direct stores, column sums ----
    if (tid < 128) scol[tid] = 0.f;
    __syncthreads();

    int g = lane >> 2;
    int t2 = (lane & 3) * 2;
    float csum[4][2];
    #pragma unroll
    for (int nt = 0; nt < 4; nt++) { csum[nt][0] = 0.f; csum[nt][1] = 0.f; }

    #pragma unroll
    for (int mt = 0; mt < 4; mt++) {
        int r0 = b0 + wm + mt * 16 + g;
        #pragma unroll
        for (int nt = 0; nt < 4; nt++) {
            int col = n0 + wn + nt * 8 + t2;
            float2 e0, e1;
            e0.x = __expf(INV_EPS * acc[mt][nt][0]);
            e0.y = __expf(INV_EPS * acc[mt][nt][1]);
            e1.x = __expf(INV_EPS * acc[mt][nt][2]);
            e1.y = __expf(INV_EPS * acc[mt][nt][3]);
            *reinterpret_cast<float2*>(&g_E[(size_t)r0 * KPAD + col]) = e0;
            *reinterpret_cast<float2*>(&g_E[(size_t)(r0 + 8) * KPAD + col]) = e1;
            csum[nt][0] += e0.x + e1.x;
            csum[nt][1] += e0.y + e1.y;
        }
    }
    #pragma unroll
    for (int nt = 0; nt < 4; nt++) {
        atomicAdd(&scol[wn + nt * 8 + t2],     csum[nt][0]);
        atomicAdd(&scol[wn + nt * 8 + t2 + 1], csum[nt][1]);
    }
    __syncthreads();

    if (tid < 128) atomicAdd(&g_u[n0 + tid], scol[tid]);  // pads land in g_u[1000..1023]
    if (tid < 32) {
        float s = 0.f;
        #pragma unroll
        for (int i = 0; i < 4; i++) {
            int k = tid + i * 32;
            if (n0 + k < KCLS) s += scol[k];
        }
        s = warp_sum(s);
        if (tid == 0) atomicAdd(&g_S, (double)s);
    }

    // ---- Last block computes r1, zeroes u ----
    __threadfence();
    __syncthreads();
    if (tid == 0) sLast = (atomicAdd(&g_cnt, 1) == GEMM_GRID - 1);
    __syncthreads();
    if (sLast) finalize_r(tid);
}

// ---------------------------------------------------------------------------
// 4. Fused pass: per row b: v_b = E[b,:].r, c_b = S/(B v_b), u += E[b,:]*c_b.
//    512 blocks x 8 warps x 3 rows. Last block computes next r, zeroes u.
// ---------------------------------------------------------------------------
#define VCU_GRID 512
__global__ __launch_bounds__(256) void k_vcu() {
    __shared__ __align__(16) float rsh[KPAD];
    __shared__ float ush[KPAD];
    __shared__ int sLast;
    for (int k = threadIdx.x; k < KPAD; k += 256) { rsh[k] = g_r[k]; ush[k] = 0.f; }
    __syncthreads();

    int tid = threadIdx.x;
    int warp = tid >> 5, lane = tid & 31;
    double Sd = g_S;
    const float4* r4 = reinterpret_cast<const float4*>(rsh);

    float uacc[32];
    #pragma unroll
    for (int i = 0; i < 32; i++) uacc[i] = 0.f;

    #pragma unroll 1
    for (int it = 0; it < 3; it++) {
        int b = blockIdx.x * 24 + warp * 3 + it;
        const float4* E4 = reinterpret_cast<const float4*>(g_E + (size_t)b * KPAD);
        float4 e[8];
        float v = 0.f;
        #pragma unroll
        for (int i = 0; i < 8; i++) {
            e[i] = E4[lane + i * 32];
            float4 r = r4[lane + i * 32];
            v += e[i].x * r.x + e[i].y * r.y + e[i].z * r.z + e[i].w * r.w;
        }
        v = warp_sum(v);
        v = __shfl_sync(0xFFFFFFFFu, v, 0);
        float cb = (float)(Sd / ((double)B_TOT * (double)v));
        #pragma unroll
        for (int i = 0; i < 8; i++) {
            uacc[i * 4 + 0] += e[i].x * cb;
            uacc[i * 4 + 1] += e[i].y * cb;
            uacc[i * 4 + 2] += e[i].z * cb;
            uacc[i * 4 + 3] += e[i].w * cb;
        }
    }
    #pragma unroll
    for (int i = 0; i < 8; i++) {
        int k0 = 4 * (lane + i * 32);
        atomicAdd(&ush[k0 + 0], uacc[i * 4 + 0]);
        atomicAdd(&ush[k0 + 1], uacc[i * 4 + 1]);
        atomicAdd(&ush[k0 + 2], uacc[i * 4 + 2]);
        atomicAdd(&ush[k0 + 3], uacc[i * 4 + 3]);
    }
    __syncthreads();
    for (int k = tid; k < KPAD; k += 256) atomicAdd(&g_u[k], ush[k]);

    // ---- Last block computes next r, zeroes u ----
    __threadfence();
    __syncthreads();
    if (tid == 0) sLast = (atomicAdd(&g_cnt, 1) == VCU_GRID - 1);
    __syncthreads();
    if (sLast) finalize_r(tid);
}

// ---------------------------------------------------------------------------
// 5. Final fused pass (rows 0..4095): v_b = E[b,:].r3 ; out = E*r3/v_b.
//    512 blocks x 8 warps x 1 row.
// ---------------------------------------------------------------------------
__global__ __launch_bounds__(256) void k_final(float* __restrict__ out) {
    __shared__ __align__(16) float rsh[KPAD];
    for (int k = threadIdx.x; k < KPAD; k += 256) rsh[k] = g_r[k];
    __syncthreads();
    int warp = threadIdx.x >> 5, lane = threadIdx.x & 31;
    const float4* r4 = reinterpret_cast<const float4*>(rsh);

    int b = blockIdx.x * 8 + warp;
    const float4* E4 = reinterpret_cast<const float4*>(g_E + (size_t)b * KPAD);
    float4 e[8];
    float v = 0.f;
    #pragma unroll
    for (int i = 0; i < 8; i++) {
        e[i] = E4[lane + i * 32];
        float4 r = r4[lane + i * 32];
        v += e[i].x * r.x + e[i].y * r.y + e[i].z * r.z + e[i].w * r.w;
    }
    v = warp_sum(v);
    v = __shfl_sync(0xFFFFFFFFu, v, 0);
    float invv = 1.0f / v;
    float* orow = out + (size_t)b * KCLS;           // 4000*b bytes: 16B aligned
    #pragma unroll
    for (int i = 0; i < 8; i++) {
        int idx = lane + i * 32;                     // float4 index, valid < 250
        if (idx < KCLS / 4) {
            float4 r = r4[idx];
            float4 o;
            o.x = e[i].x * r.x * invv;
            o.y = e[i].y * r.y * invv;
            o.z = e[i].z * r.z * invv;
            o.w = e[i].w * r.w * invv;
            *reinterpret_cast<float4*>(orow + idx * 4) = o;
        }
    }
}

// ---------------------------------------------------------------------------
extern "C" void kernel_launch(void* const* d_in, const int* in_sizes, int n_in,
                              void* d_out, int out_size) {
    const float* features = (const float*)d_in[0];
    const float* head     = (const float*)d_in[1];
    const float* queue    = (const float*)d_in[2];
    float* out = (float*)d_out;

    cudaFuncSetAttribute(k_gemm_mma, cudaFuncAttributeMaxDynamicSharedMemorySize,
                         SMEM_GEMM_TOTAL);

    k_prep_feat<<<(B_TOT * 32) / 256, 256>>>(features, queue);
    k_prep_head<<<DDIM, 256>>>(head);
    k_gemm_mma<<<dim3(KPAD / 128, B_TOT / 128), 256, SMEM_GEMM_TOTAL>>>();  // + r1
    k_vcu<<<VCU_GRID, 256>>>();   // iter1 col-step + iter2 row-sum -> r2
    k_vcu<<<VCU_GRID, 256>>>();   // iter2 col-step + iter3 row-sum -> r3
    k_final<<<512, 256>>>(out);   // iter3 col-step fused with output
}